// round 2
// baseline (speedup 1.0000x reference)
#include <cuda_runtime.h>

// x: (B=64, W=512, H=48, M=64) fp32, row-major.
// out[b, ((iw*6 + ih)*64 + m)] = max over w in [iw*32, iw*32+32), h in [ih*8, ih*8+8).
// Bins are exact: 512/16 = 32, 48/6 = 8.
//
// One CTA per (b, iw): streams a fully contiguous 32*48*64*4 = 384 KB range,
// producing all 6 ih bins. 1024 CTAs total (~1 wave at ~7 CTAs/SM).

constexpr int B_  = 64;
constexpr int W_  = 512;
constexpr int H_  = 48;
constexpr int M_  = 64;
constexpr int M4  = M_ / 4;   // 16 float4 lanes over M
constexpr int PW  = 16;
constexpr int PH  = 6;
constexpr int WB  = W_ / PW;  // 32
constexpr int HB  = H_ / PH;  // 8

__device__ __forceinline__ float4 max4(float4 a, float4 b) {
    float4 r;
    r.x = fmaxf(a.x, b.x);
    r.y = fmaxf(a.y, b.y);
    r.z = fmaxf(a.z, b.z);
    r.w = fmaxf(a.w, b.w);
    return r;
}

__global__ __launch_bounds__(256)
void dap_pool_kernel(const float4* __restrict__ x4, float4* __restrict__ out4) {
    const int iw = blockIdx.x;   // 0..15
    const int b  = blockIdx.y;   // 0..63

    const int tid = threadIdx.x; // 0..255
    const int m4  = tid & 15;    // float4 lane over M
    const int sub = tid >> 4;    // 0..15 window subsets

    // Base of this CTA's contiguous 384 KB range (in float4 units).
    const float4* __restrict__ xb =
        x4 + ((size_t)b * W_ * H_ + (size_t)iw * WB * H_) * M4;

    // Partials: smem[sub][ih][m4]
    __shared__ float4 smem[16][PH][M4];

    // One ih bin at a time: 256 cells (32 w x 8 h), each sub covers 16 cells.
    // Single accumulator keeps regs low; 16 unrolled independent loads = MLP 16.
#pragma unroll
    for (int ih = 0; ih < PH; ih++) {
        float4 acc = make_float4(-INFINITY, -INFINITY, -INFINITY, -INFINITY);
#pragma unroll
        for (int i = 0; i < 16; i++) {
            const int c  = sub + (i << 4);   // 0..255
            const int wl = c >> 3;           // 0..31
            const int hl = c & 7;            // 0..7
            const float4 v =
                __ldcs(&xb[((size_t)wl * H_ + ih * HB + hl) * M4 + m4]);
            acc = max4(acc, v);
        }
        smem[sub][ih][m4] = acc;
    }
    __syncthreads();

    // Reduce the 16 subsets; 96 threads (6 bins x 16 m4 lanes) each do 16 LDS.
    if (tid < PH * M4) {
        const int ih = tid >> 4;
        const int m  = tid & 15;
        float4 r = smem[0][ih][m];
#pragma unroll
        for (int s = 1; s < 16; s++) r = max4(r, smem[s][ih][m]);
        out4[(size_t)b * (PW * PH * M4) + (size_t)(iw * PH + ih) * M4 + m] = r;
    }
}

extern "C" void kernel_launch(void* const* d_in, const int* in_sizes, int n_in,
                              void* d_out, int out_size) {
    const float4* x4 = (const float4*)d_in[0];
    float4* out4 = (float4*)d_out;
    dim3 grid(PW, B_);
    dap_pool_kernel<<<grid, 256>>>(x4, out4);
}

// round 5
// speedup vs baseline: 1.0324x; 1.0324x over previous
#include <cuda_runtime.h>

// x: (B=64, W=512, H=48, M=64) fp32, row-major.
// out[b, ((iw*6 + ih)*64 + m)] = max over w in [iw*32, iw*32+32), h in [ih*8, ih*8+8).
// Exact bins: 512/16 = 32, 48/6 = 8.
//
// R1 structure (one CTA per (b,iw,ih), 6144 CTAs, 256 thr, occ ~96%) plus:
//   - __ldcs streaming loads (each byte touched exactly once)
//   - blockIdx.x = ih so consecutively-scheduled CTAs read adjacent 2KB chunks
//   - two 8-deep load batches seeded by their first load (no -inf init)
//   - single-barrier tail reduction

constexpr int B_  = 64;
constexpr int W_  = 512;
constexpr int H_  = 48;
constexpr int M_  = 64;
constexpr int M4  = M_ / 4;   // 16
constexpr int PW  = 16;
constexpr int PH  = 6;
constexpr int WB  = W_ / PW;  // 32
constexpr int HB  = H_ / PH;  // 8

__device__ __forceinline__ float4 max4(float4 a, float4 b) {
    float4 r;
    r.x = fmaxf(a.x, b.x);
    r.y = fmaxf(a.y, b.y);
    r.z = fmaxf(a.z, b.z);
    r.w = fmaxf(a.w, b.w);
    return r;
}

__global__ __launch_bounds__(256, 8)
void dap_pool_kernel(const float4* __restrict__ x4, float4* __restrict__ out4) {
    const int ih = blockIdx.x;   // 0..5  (fastest: adjacent CTAs -> adjacent chunks)
    const int iw = blockIdx.y;   // 0..15
    const int b  = blockIdx.z;   // 0..63

    const int tid = threadIdx.x;       // 0..255
    const int m4  = tid & 15;          // float4 lane over M
    const int sub = tid >> 4;          // 0..15 window subsets

    const float4* __restrict__ xb =
        x4 + ((size_t)b * W_ * H_ + (size_t)(iw * WB) * H_ + (size_t)(ih * HB)) * M4
           + m4;

    // Per-thread cells: c = sub + 16*i, i in [0,16). wl = c>>3, hl = c&7.
    // Two 8-deep batches with independent accumulators, each seeded by its
    // first load.
    float4 acc0, acc1;
    {
        const int c = sub;
        acc0 = __ldcs(xb + ((size_t)(c >> 3) * H_ + (c & 7)) * M4);
    }
#pragma unroll
    for (int i = 1; i < 8; i++) {
        const int c = sub + (i << 4);
        acc0 = max4(acc0, __ldcs(xb + ((size_t)(c >> 3) * H_ + (c & 7)) * M4));
    }
    {
        const int c = sub + (8 << 4);
        acc1 = __ldcs(xb + ((size_t)(c >> 3) * H_ + (c & 7)) * M4);
    }
#pragma unroll
    for (int i = 9; i < 16; i++) {
        const int c = sub + (i << 4);
        acc1 = max4(acc1, __ldcs(xb + ((size_t)(c >> 3) * H_ + (c & 7)) * M4));
    }

    // Single-barrier reduction: smem[sub][m4], 16 threads fold 16 subsets.
    __shared__ float4 smem[16][M4];
    smem[sub][m4] = max4(acc0, acc1);
    __syncthreads();

    if (tid < M4) {
        float4 r = smem[0][tid];
#pragma unroll
        for (int s = 1; s < 16; s++) r = max4(r, smem[s][tid]);
        out4[(size_t)b * (PW * PH * M4) + (size_t)(iw * PH + ih) * M4 + tid] = r;
    }
}

extern "C" void kernel_launch(void* const* d_in, const int* in_sizes, int n_in,
                              void* d_out, int out_size) {
    const float4* x4 = (const float4*)d_in[0];
    float4* out4 = (float4*)d_out;
    dim3 grid(PH, PW, B_);
    dap_pool_kernel<<<grid, 256>>>(x4, out4);
}

// round 6
// speedup vs baseline: 1.0367x; 1.0041x over previous
#include <cuda_runtime.h>

// x: (B=64, W=512, H=48, M=64) fp32, row-major.
// out[b, ((iw*6 + ih)*64 + m)] = max over w in [iw*32, iw*32+32), h in [ih*8, ih*8+8).
// Exact bins: 512/16 = 32, 48/6 = 8.
//
// Measured-best configuration:
//   - one CTA per (b,iw,ih): 6144 CTAs x 256 thr, 32 regs, occ 8/SM (R1: DRAM 85.6%)
//   - single 16-deep fully-unrolled __ldg batch, one accumulator (MLP_p1=16)
//   - ih-fastest grid order, single-barrier tail reduction (neutral tail savings)

constexpr int B_  = 64;
constexpr int W_  = 512;
constexpr int H_  = 48;
constexpr int M_  = 64;
constexpr int M4  = M_ / 4;   // 16
constexpr int PW  = 16;
constexpr int PH  = 6;
constexpr int WB  = W_ / PW;  // 32
constexpr int HB  = H_ / PH;  // 8

__device__ __forceinline__ float4 max4(float4 a, float4 b) {
    float4 r;
    r.x = fmaxf(a.x, b.x);
    r.y = fmaxf(a.y, b.y);
    r.z = fmaxf(a.z, b.z);
    r.w = fmaxf(a.w, b.w);
    return r;
}

__global__ __launch_bounds__(256, 8)
void dap_pool_kernel(const float4* __restrict__ x4, float4* __restrict__ out4) {
    const int ih = blockIdx.x;   // 0..5
    const int iw = blockIdx.y;   // 0..15
    const int b  = blockIdx.z;   // 0..63

    const int tid = threadIdx.x;       // 0..255
    const int m4  = tid & 15;          // float4 lane over M
    const int sub = tid >> 4;          // 0..15 window subsets

    const float4* __restrict__ xb =
        x4 + ((size_t)b * W_ * H_ + (size_t)(iw * WB) * H_ + (size_t)(ih * HB)) * M4;

    // Window: 32w x 8h = 256 cells; each thread covers 16 cells c = sub + 16*i,
    // fully unrolled in one batch (MLP 16), single accumulator.
    float4 acc = make_float4(-INFINITY, -INFINITY, -INFINITY, -INFINITY);
#pragma unroll
    for (int i = 0; i < 16; i++) {
        const int c  = sub + (i << 4);     // 0..255
        const int wl = c >> 3;             // 0..31
        const int hl = c & 7;              // 0..7
        const float4 v = __ldg(&xb[((size_t)wl * H_ + hl) * M4 + m4]);
        acc = max4(acc, v);
    }

    // Single-barrier reduction: smem[sub][m4], then 16 threads fold 16 subsets.
    __shared__ float4 smem[16][M4];
    smem[sub][m4] = acc;
    __syncthreads();

    if (tid < M4) {
        float4 r = smem[0][tid];
#pragma unroll
        for (int s = 1; s < 16; s++) r = max4(r, smem[s][tid]);
        out4[(size_t)b * (PW * PH * M4) + (size_t)(iw * PH + ih) * M4 + tid] = r;
    }
}

extern "C" void kernel_launch(void* const* d_in, const int* in_sizes, int n_in,
                              void* d_out, int out_size) {
    const float4* x4 = (const float4*)d_in[0];
    float4* out4 = (float4*)d_out;
    dim3 grid(PH, PW, B_);
    dap_pool_kernel<<<grid, 256>>>(x4, out4);
}